// round 12
// baseline (speedup 1.0000x reference)
#include <cuda_runtime.h>
#include <cuda_bf16.h>
#include <cstdint>
#include <math.h>

#define NPTS  32768
#define CIN   64
#define NHD   16
#define CQ    1024
#define LNEPS 1e-5f

// ---------------- helpers ----------------
__device__ __forceinline__ uint32_t smem_u32(const void* p) {
    uint32_t a;
    asm("{ .reg .u64 t; cvta.to.shared.u64 t, %1; cvt.u32.u64 %0, t; }" : "=r"(a) : "l"(p));
    return a;
}
__device__ __forceinline__ void ldsm_x4(uint32_t r[4], uint32_t addr) {
    asm volatile("ldmatrix.sync.aligned.m8n8.x4.shared.b16 {%0,%1,%2,%3}, [%4];"
                 : "=r"(r[0]), "=r"(r[1]), "=r"(r[2]), "=r"(r[3]) : "r"(addr));
}
__device__ __forceinline__ void mma_bf16(float c[4], const uint32_t a[4], uint32_t b0, uint32_t b1) {
    asm volatile("mma.sync.aligned.m16n8k16.row.col.f32.bf16.bf16.f32 "
                 "{%0,%1,%2,%3}, {%4,%5,%6,%7}, {%8,%9}, {%0,%1,%2,%3};"
                 : "+f"(c[0]), "+f"(c[1]), "+f"(c[2]), "+f"(c[3])
                 : "r"(a[0]), "r"(a[1]), "r"(a[2]), "r"(a[3]), "r"(b0), "r"(b1));
}
__device__ __forceinline__ uint32_t pkb(__nv_bfloat16 a, __nv_bfloat16 b) {
    return (uint32_t)__bfloat16_as_ushort(a) | ((uint32_t)__bfloat16_as_ushort(b) << 16);
}
#define CP16(dst, src) \
    asm volatile("cp.async.ca.shared.global [%0], [%1], 16;" :: "r"((uint32_t)(dst)), "l"(src))
#define CP_COMMIT() asm volatile("cp.async.commit_group;")
#define CP_WAIT0()  asm volatile("cp.async.wait_group 0;" ::: "memory")
#define CP_WAIT1()  asm volatile("cp.async.wait_group 1;" ::: "memory")

// ---------------- scratch ----------------
__device__ uint32_t g_xfh [NPTS * 64];   // LN(F) bf16 split, [p][word]: 0-31 hi pairs, 32-63 lo pairs
__device__ uint32_t g_xmh [NPTS * 64];   // LN(M) bf16 split, same layout
__device__ uint32_t g_qmA [NPTS * 1024]; // qm bf16 split in mma A-fragment layout: [p][lane32][reg4][kc8]
__device__ uint32_t g_GtA [CQ * 64];     // [n][word]: [hi | lo]
__device__ uint32_t g_GtB [CQ * 64];     // [n][word]: [lo | hi]
__device__ float    g_u   [CQ];

// ---------------- kernel 0: fused weights G = Wf Wm^T (bf16 split) + u ----------------
__global__ __launch_bounds__(256) void precompute_kernel(
    const float* __restrict__ wf, const float* __restrict__ wm,
    const float* __restrict__ bf)
{
    int h = blockIdx.x;
    __shared__ float wfs[64][65];
    __shared__ float wms[64][65];
    int tid = threadIdx.x;
    for (int idx = tid; idx < 4096; idx += 256) {
        int r = idx >> 6, d = idx & 63;
        wfs[r][d] = wf[r * CQ + h * 64 + d];
        wms[r][d] = wm[r * CQ + h * 64 + d];
    }
    __syncthreads();
    for (int idx = tid; idx < 2048; idx += 256) {
        int i2 = idx >> 6, j = idx & 63;
        float s0 = 0.f, s1 = 0.f;
        #pragma unroll
        for (int d = 0; d < 64; d++) {
            s0 += wfs[2 * i2][d] * wms[j][d];
            s1 += wfs[2 * i2 + 1][d] * wms[j][d];
        }
        __nv_bfloat16 h0 = __float2bfloat16_rn(s0), h1 = __float2bfloat16_rn(s1);
        __nv_bfloat16 l0 = __float2bfloat16_rn(s0 - __bfloat162float(h0));
        __nv_bfloat16 l1 = __float2bfloat16_rn(s1 - __bfloat162float(h1));
        int n = h * 64 + j;
        uint32_t hp = pkb(h0, h1), lp = pkb(l0, l1);
        g_GtA[n * 64 + i2]      = hp;
        g_GtA[n * 64 + 32 + i2] = lp;
        g_GtB[n * 64 + i2]      = lp;
        g_GtB[n * 64 + 32 + i2] = hp;
    }
    if (tid < 64) {
        float s = 0.f;
        #pragma unroll
        for (int d = 0; d < 64; d++) s += wms[tid][d] * bf[h * 64 + d];
        g_u[h * 64 + tid] = s;
    }
}

// ---------------- kernel 1: LayerNorm -> bf16 split rows ----------------
__global__ __launch_bounds__(128) void ln_kernel(
    const float* __restrict__ src,
    const float* __restrict__ gamma, const float* __restrict__ beta,
    int which)   // 0 -> g_xfh ; 1 -> g_xmh
{
    __shared__ float gs[64], bs[64];
    int tid = threadIdx.x;
    if (tid < 64) { gs[tid] = gamma[tid]; bs[tid] = beta[tid]; }
    __syncthreads();

    int p = blockIdx.x * 128 + tid;
    float v[64];
    float mean = 0.f;
    #pragma unroll
    for (int c = 0; c < 64; c++) { v[c] = src[c * NPTS + p]; mean += v[c]; }
    mean *= (1.f / 64.f);
    float var = 0.f;
    #pragma unroll
    for (int c = 0; c < 64; c++) { float d = v[c] - mean; var += d * d; }
    float rstd = rsqrtf(var * (1.f / 64.f) + LNEPS);

    uint32_t* dst = which ? g_xmh : g_xfh;
    #pragma unroll
    for (int c8 = 0; c8 < 64; c8 += 8) {
        uint32_t hw[4], lw[4];
        #pragma unroll
        for (int j = 0; j < 4; j++) {
            int c = c8 + 2 * j;
            float y0 = (v[c] - mean) * rstd * gs[c] + bs[c];
            float y1 = (v[c + 1] - mean) * rstd * gs[c + 1] + bs[c + 1];
            __nv_bfloat16 h0 = __float2bfloat16_rn(y0), h1 = __float2bfloat16_rn(y1);
            __nv_bfloat16 l0 = __float2bfloat16_rn(y0 - __bfloat162float(h0));
            __nv_bfloat16 l1 = __float2bfloat16_rn(y1 - __bfloat162float(h1));
            hw[j] = pkb(h0, h1);
            lw[j] = pkb(l0, l1);
        }
        *(uint4*)&dst[p * 64 + (c8 >> 1)]      = make_uint4(hw[0], hw[1], hw[2], hw[3]);
        *(uint4*)&dst[p * 64 + 32 + (c8 >> 1)] = make_uint4(lw[0], lw[1], lw[2], lw[3]);
    }
}

// ---------------- kernel 2: qm GEMM via mma.sync bf16 (split, exact) ----------------
// B-resident m-loop (R6 mainloop). Epilogue emits bf16-split qm in A-fragment
// layout g_qmA[p][lane][reg][kc] so the attention kernel LDGs A-frags directly.
#define GEMM_SMEM (98304)

__global__ __launch_bounds__(256, 2) void qm_gemm_mma()
{
    extern __shared__ char smg[];
    __shared__ float su[128];
    int tid = threadIdx.x;
    int wid = tid >> 5, lane = tid & 31;
    int n0 = blockIdx.x * 128;
    int p0 = blockIdx.y * 512;
    int wm = wid & 1, wn = wid >> 1;

    if (tid < 128) su[tid] = g_u[n0 + tid];

    uint32_t smb = smem_u32(smg);
    const uint4* xf4 = (const uint4*)g_xfh;
    const uint4* GA  = (const uint4*)g_GtA;
    const uint4* GB  = (const uint4*)g_GtB;

    #pragma unroll
    for (int i = tid; i < 2048; i += 256) {
        int r = i >> 4, c = i & 15;
        uint32_t dst = r * 256 + ((c ^ (r & 7)) << 4);
        CP16(smb + 32768 + dst, &GA[(n0 + r) * 16 + c]);
        CP16(smb + 65536 + dst, &GB[(n0 + r) * 16 + c]);
    }
    #pragma unroll
    for (int i = tid; i < 1024; i += 256) {
        int r = i >> 4, c = i & 15;
        uint32_t dst = r * 256 + ((c ^ (r & 7)) << 4);
        CP16(smb + dst, &xf4[(p0 + r) * 16 + c]);
    }
    CP_COMMIT();

    int arow = wm * 32 + (lane & 15);
    int ach  = lane >> 4;
    int brow = wn * 32 + (lane & 7) + ((lane >> 4) << 3);
    int bch  = (lane >> 3) & 1;
    int g = lane >> 2, t4 = lane & 3;

    #pragma unroll 1
    for (int t = 0; t < 8; t++) {
        __syncthreads();
        if (t < 7) {
            uint32_t abase = ((t + 1) & 1) ? 16384u : 0u;
            int pr = p0 + (t + 1) * 64;
            #pragma unroll
            for (int i = tid; i < 1024; i += 256) {
                int r = i >> 4, c = i & 15;
                uint32_t dst = abase + r * 256 + ((c ^ (r & 7)) << 4);
                CP16(smb + dst, &xf4[(pr + r) * 16 + c]);
            }
            CP_COMMIT();
            CP_WAIT1();
        } else {
            CP_WAIT0();
        }
        __syncthreads();

        uint32_t abase = (t & 1) ? 16384u : 0u;
        float acc[2][4][4];
        #pragma unroll
        for (int mi = 0; mi < 2; mi++)
            #pragma unroll
            for (int ni = 0; ni < 4; ni++)
                #pragma unroll
                for (int e = 0; e < 4; e++) acc[mi][ni][e] = 0.f;

        #pragma unroll
        for (int ks = 0; ks < 16; ks++) {
            int kk = ks & 7;
            uint32_t boff = (ks < 8) ? 32768u : 65536u;
            uint32_t a[2][4];
            #pragma unroll
            for (int mi = 0; mi < 2; mi++) {
                int row = arow + mi * 16;
                int ch  = kk * 2 + ach;
                ldsm_x4(a[mi], smb + abase + row * 256 + ((ch ^ (row & 7)) << 4));
            }
            uint32_t b[2][4];
            #pragma unroll
            for (int nj = 0; nj < 2; nj++) {
                int row = brow + nj * 16;
                int ch  = kk * 2 + bch;
                ldsm_x4(b[nj], smb + boff + row * 256 + ((ch ^ (row & 7)) << 4));
            }
            #pragma unroll
            for (int mi = 0; mi < 2; mi++)
                #pragma unroll
                for (int nj = 0; nj < 2; nj++) {
                    mma_bf16(acc[mi][2 * nj + 0], a[mi], b[nj][0], b[nj][1]);
                    mma_bf16(acc[mi][2 * nj + 1], a[mi], b[nj][2], b[nj][3]);
                }
        }

        // epilogue: += u, bf16 split, store A-fragment layout
        #pragma unroll
        for (int mi = 0; mi < 2; mi++) {
            int pA = p0 + t * 64 + wm * 32 + mi * 16 + g;
            #pragma unroll
            for (int ni = 0; ni < 4; ni++) {
                int nl = wn * 32 + ni * 8 + 2 * t4;       // even channel pair (c, c+1)
                int h  = (n0 + nl) >> 6;                  // head 0..15 = A row
                int c  = nl & 63;
                int kr = c & 15;
                int tt = (kr >> 1) & 3;
                int reg = ((h & 8) ? 1 : 0) + ((kr & 8) ? 2 : 0);
                int flane = (h & 7) * 4 + tt;
                int kch = c >> 4, kcl = kch + 4;
                float u0 = su[nl], u1 = su[nl + 1];
                float v0 = acc[mi][ni][0] + u0, v1 = acc[mi][ni][1] + u1;
                float v2 = acc[mi][ni][2] + u0, v3 = acc[mi][ni][3] + u1;

                __nv_bfloat16 h0 = __float2bfloat16_rn(v0), h1 = __float2bfloat16_rn(v1);
                __nv_bfloat16 l0 = __float2bfloat16_rn(v0 - __bfloat162float(h0));
                __nv_bfloat16 l1 = __float2bfloat16_rn(v1 - __bfloat162float(h1));
                __nv_bfloat16 h2 = __float2bfloat16_rn(v2), h3 = __float2bfloat16_rn(v3);
                __nv_bfloat16 l2 = __float2bfloat16_rn(v2 - __bfloat162float(h2));
                __nv_bfloat16 l3 = __float2bfloat16_rn(v3 - __bfloat162float(h3));

                int baseA = pA * 1024 + flane * 32 + reg * 8;
                int baseB = (pA + 8) * 1024 + flane * 32 + reg * 8;
                g_qmA[baseA + kch] = pkb(h0, h1);
                g_qmA[baseA + kcl] = pkb(l0, l1);
                g_qmA[baseB + kch] = pkb(h2, h3);
                g_qmA[baseB + kcl] = pkb(l2, l3);
            }
        }
    }
}

// ---------------- kernel 3: HMMA neighborhood attention ----------------
// One warp per point. Per point: S[16 heads][32 offsets(27 real)] via
// mma.m16n8k16, K=128 bf16 exact split (pass2 pairs a[kc] with b[kc^4]).
// A-frags: 8 coalesced LDG.128/lane from g_qmA. B-frags: ldmatrix from a bf16
// halo with strides TS=17/YS=579/ZS=2321 (16B units) — conflict-free phases.
#define TSC 17
#define YSC 579
#define ZSC 2321
#define SCRC 9283
#define HALO_BYTES (9303 * 16)

__global__ __launch_bounds__(256) void attn_kernel(
    const float* __restrict__ rpb, float* __restrict__ out)
{
    extern __shared__ uint4 halo4[];
    __shared__ float rpb_s[NHD * 27];
    int tid = threadIdx.x;
    int z0 = (blockIdx.x >> 4) * 2;
    int y0 = (blockIdx.x & 15) * 2;

    for (int i = tid; i < NHD * 27; i += 256) rpb_s[i] = rpb[i];

    const uint4* xmh4 = (const uint4*)g_xmh;
    for (int i = tid; i < 8704; i += 256) {        // 544 positions x 16 chunks
        int pos = i >> 4, c = i & 15;
        int z = pos / 136;
        int r = pos - z * 136;
        int y = r / 34;
        int t = r - y * 34;
        int gz = z0 - 1 + z, gy = y0 - 1 + y, gt = t - 1;
        uint4 v = make_uint4(0, 0, 0, 0);
        if ((unsigned)gz < 32u && (unsigned)gy < 32u && (unsigned)gt < 32u)
            v = xmh4[(gz * 1024 + gy * 32 + gt) * 16 + c];
        halo4[z * ZSC + y * YSC + t * TSC + c] = v;
    }
    for (int i = tid; i < 20; i += 256) halo4[SCRC + i] = make_uint4(0, 0, 0, 0);
    __syncthreads();

    int warp = tid >> 5, lane = tid & 31;
    int pz = warp & 1, py = (warp >> 1) & 1, th = warp >> 2;
    int g = lane >> 2, t4 = lane & 3;

    // B-side per-lane row (offset) addressing, GEMM-proven ldsm pattern
    int orow  = (lane & 7) + ((lane >> 4) << 3);   // 0..15
    int bhalf = (lane >> 3) & 1;
    int brel[2], bsel[2];
    #pragma unroll
    for (int ng = 0; ng < 2; ng++) {
        int o = orow + ng * 16;
        if (o < 27) {
            int dz = o / 9, rr = o - dz * 9, dy = rr / 3, dx = rr - dy * 3;
            brel[ng] = dz * ZSC + dy * YSC + dx * TSC;
            bsel[ng] = 1;
        } else {
            brel[ng] = SCRC + (o - 27);
            bsel[ng] = 0;
        }
    }
    uint32_t halob = smem_u32(halo4);

    // per-lane rpb / value-grid weights / pad mask for my 8 score slots
    float rpbA[8], rpbB[8], wz[8], wy[8], wt[8], msk[8];
    #pragma unroll
    for (int i = 0; i < 8; i++) {
        int nt = i >> 1, j = i & 1, o = nt * 8 + 2 * t4 + j;
        if (o < 27) {
            int dz = o / 9, rr = o - dz * 9, dy = rr / 3, dx = rr - dy * 3;
            rpbA[i] = rpb_s[g * 27 + o];
            rpbB[i] = rpb_s[(g + 8) * 27 + o];
            wz[i] = (float)(dz - 1); wy[i] = (float)(dy - 1); wt[i] = (float)(dx - 1);
            msk[i] = 1.f;
        } else {
            rpbA[i] = 0.f; rpbB[i] = 0.f; wz[i] = 0.f; wy[i] = 0.f; wt[i] = 0.f; msk[i] = 0.f;
        }
    }

    const uint4* qmA4 = (const uint4*)g_qmA;
    int gp0 = (z0 + pz) * 1024 + (y0 + py) * 32 + th * 16;
    int pb0 = pz * ZSC + py * YSC + (th * 16) * TSC;

    // A-frag prefetch for first point
    uint4 A4[8], A4n[8];
    {
        const uint4* ap = &qmA4[(gp0 * 32 + lane) * 8];
        #pragma unroll
        for (int j = 0; j < 8; j++) A4[j] = ap[j];
    }

    #pragma unroll 1
    for (int i16 = 0; i16 < 16; i16++) {
        int gp = gp0 + i16;
        int pbase = pb0 + i16 * TSC;

        if (i16 < 15) {
            const uint4* ap = &qmA4[((gp + 1) * 32 + lane) * 8];
            #pragma unroll
            for (int j = 0; j < 8; j++) A4n[j] = ap[j];
        }

        // B fragments: 16 ldmatrix.x4
        uint32_t b[2][8][4];
        #pragma unroll
        for (int ng = 0; ng < 2; ng++) {
            int basech = bsel[ng] * pbase + brel[ng] + bhalf;
            #pragma unroll
            for (int kc = 0; kc < 8; kc++)
                ldsm_x4(b[ng][kc], halob + (uint32_t)(basech + kc * 2) * 16u);
        }

        float acc[4][4];
        #pragma unroll
        for (int nt = 0; nt < 4; nt++)
            #pragma unroll
            for (int e = 0; e < 4; e++) acc[nt][e] = 0.f;

        const uint32_t* aw = (const uint32_t*)A4;
        #pragma unroll
        for (int kc = 0; kc < 8; kc++) {
            uint32_t a[4];
            a[0] = aw[((kc >> 2) + 0) * 4 + (kc & 3)];
            a[1] = aw[((kc >> 2) + 2) * 4 + (kc & 3)];
            a[2] = aw[((kc >> 2) + 4) * 4 + (kc & 3)];
            a[3] = aw[((kc >> 2) + 6) * 4 + (kc & 3)];
            int k2 = kc ^ 4;
            #pragma unroll
            for (int nt = 0; nt < 4; nt++) {
                int ng = nt >> 1, hf = (nt & 1) * 2;
                mma_bf16(acc[nt], a, b[ng][kc][hf], b[ng][kc][hf + 1]);   // hi*hi + lo*lo
                mma_bf16(acc[nt], a, b[ng][k2][hf], b[ng][k2][hf + 1]);   // hi*lo + lo*hi
            }
        }

        // register softmax + value-grid projection (heads g and g+8)
        float S0 = 0.f, Z0 = 0.f, Y0 = 0.f, T0 = 0.f;
        float S1 = 0.f, Z1 = 0.f, Y1 = 0.f, T1 = 0.f;
        #pragma unroll
        for (int i = 0; i < 8; i++) {
            int nt = i >> 1, j = i & 1;
            float e0 = __expf(acc[nt][j]     + rpbA[i]) * msk[i];
            float e1 = __expf(acc[nt][2 + j] + rpbB[i]) * msk[i];
            S0 += e0; Z0 += e0 * wz[i]; Y0 += e0 * wy[i]; T0 += e0 * wt[i];
            S1 += e1; Z1 += e1 * wz[i]; Y1 += e1 * wy[i]; T1 += e1 * wt[i];
        }
        #pragma unroll
        for (int m = 1; m < 4; m <<= 1) {
            S0 += __shfl_xor_sync(0xffffffffu, S0, m);
            Z0 += __shfl_xor_sync(0xffffffffu, Z0, m);
            Y0 += __shfl_xor_sync(0xffffffffu, Y0, m);
            T0 += __shfl_xor_sync(0xffffffffu, T0, m);
            S1 += __shfl_xor_sync(0xffffffffu, S1, m);
            Z1 += __shfl_xor_sync(0xffffffffu, Z1, m);
            Y1 += __shfl_xor_sync(0xffffffffu, Y1, m);
            T1 += __shfl_xor_sync(0xffffffffu, T1, m);
        }
        if (t4 == 0) {
            float i0 = 1.f / S0, i1 = 1.f / S1;
            out[(g * 3 + 0) * NPTS + gp] = Z0 * i0;
            out[(g * 3 + 1) * NPTS + gp] = Y0 * i0;
            out[(g * 3 + 2) * NPTS + gp] = T0 * i0;
            out[((g + 8) * 3 + 0) * NPTS + gp] = Z1 * i1;
            out[((g + 8) * 3 + 1) * NPTS + gp] = Y1 * i1;
            out[((g + 8) * 3 + 2) * NPTS + gp] = T1 * i1;
        }

        #pragma unroll
        for (int j = 0; j < 8; j++) A4[j] = A4n[j];
    }
}

// ---------------- launch ----------------
extern "C" void kernel_launch(void* const* d_in, const int* in_sizes, int n_in,
                              void* d_out, int out_size)
{
    const float* F       = (const float*)d_in[0];
    const float* M       = (const float*)d_in[1];
    const float* gamma_f = (const float*)d_in[2];
    const float* beta_f  = (const float*)d_in[3];
    const float* w_f     = (const float*)d_in[4];
    const float* b_f     = (const float*)d_in[5];
    const float* gamma_m = (const float*)d_in[6];
    const float* beta_m  = (const float*)d_in[7];
    const float* w_m     = (const float*)d_in[8];
    /* b_m (d_in[9]) is softmax-invariant and drops out */
    const float* rpb     = (const float*)d_in[10];
    float* out = (float*)d_out;

    precompute_kernel<<<16, 256>>>(w_f, w_m, b_f);
    ln_kernel<<<NPTS / 128, 128>>>(F, gamma_f, beta_f, 0);
    ln_kernel<<<NPTS / 128, 128>>>(M, gamma_m, beta_m, 1);

    cudaFuncSetAttribute(qm_gemm_mma, cudaFuncAttributeMaxDynamicSharedMemorySize, GEMM_SMEM);
    qm_gemm_mma<<<dim3(8, 64), 256, GEMM_SMEM>>>();

    cudaFuncSetAttribute(attn_kernel, cudaFuncAttributeMaxDynamicSharedMemorySize, HALO_BYTES);
    attn_kernel<<<256, 256, HALO_BYTES>>>(rpb, out);
}

// round 13
// speedup vs baseline: 1.5809x; 1.5809x over previous
#include <cuda_runtime.h>
#include <cuda_bf16.h>
#include <cstdint>
#include <math.h>

#define NPTS  32768
#define CIN   64
#define NHD   16
#define CQ    1024
#define LNEPS 1e-5f

// ---------------- helpers ----------------
__device__ __forceinline__ uint32_t smem_u32(const void* p) {
    uint32_t a;
    asm("{ .reg .u64 t; cvta.to.shared.u64 t, %1; cvt.u32.u64 %0, t; }" : "=r"(a) : "l"(p));
    return a;
}
__device__ __forceinline__ void ldsm_x4(uint32_t r[4], uint32_t addr) {
    asm volatile("ldmatrix.sync.aligned.m8n8.x4.shared.b16 {%0,%1,%2,%3}, [%4];"
                 : "=r"(r[0]), "=r"(r[1]), "=r"(r[2]), "=r"(r[3]) : "r"(addr));
}
__device__ __forceinline__ void mma_bf16(float c[4], const uint32_t a[4], uint32_t b0, uint32_t b1) {
    asm volatile("mma.sync.aligned.m16n8k16.row.col.f32.bf16.bf16.f32 "
                 "{%0,%1,%2,%3}, {%4,%5,%6,%7}, {%8,%9}, {%0,%1,%2,%3};"
                 : "+f"(c[0]), "+f"(c[1]), "+f"(c[2]), "+f"(c[3])
                 : "r"(a[0]), "r"(a[1]), "r"(a[2]), "r"(a[3]), "r"(b0), "r"(b1));
}
__device__ __forceinline__ uint32_t pkb(__nv_bfloat16 a, __nv_bfloat16 b) {
    return (uint32_t)__bfloat16_as_ushort(a) | ((uint32_t)__bfloat16_as_ushort(b) << 16);
}
#define CP16(dst, src) \
    asm volatile("cp.async.ca.shared.global [%0], [%1], 16;" :: "r"((uint32_t)(dst)), "l"(src))
#define CP_COMMIT() asm volatile("cp.async.commit_group;")
#define CP_WAIT0()  asm volatile("cp.async.wait_group 0;" ::: "memory")
#define CP_WAIT1()  asm volatile("cp.async.wait_group 1;" ::: "memory")

// ---------------- scratch ----------------
__device__ __align__(16) uint32_t g_xfh [NPTS * 64];   // LN(F) bf16 split, [p][word]
__device__ __align__(16) uint32_t g_xmh [NPTS * 64];   // LN(M) bf16 split
// qm bf16 split, per point 1024 words: word = ln*32 + hb*16 + hilo*8 + (cph>>2),
// ln = (h&7)*4 + (cph&3), hb = h>>3.  Attention lane L reads words 32L..32L+31.
__device__ __align__(16) uint32_t g_qmA [NPTS * 1024];
__device__ __align__(16) uint32_t g_GtA [CQ * 64];     // [n][word]: [hi | lo]
__device__ __align__(16) uint32_t g_GtB [CQ * 64];     // [n][word]: [lo | hi]
__device__ float    g_u   [CQ];

// ---------------- kernel 0: fused weights G = Wf Wm^T (bf16 split) + u ----------------
__global__ __launch_bounds__(256) void precompute_kernel(
    const float* __restrict__ wf, const float* __restrict__ wm,
    const float* __restrict__ bf)
{
    int h = blockIdx.x;
    __shared__ float wfs[64][65];
    __shared__ float wms[64][65];
    int tid = threadIdx.x;
    for (int idx = tid; idx < 4096; idx += 256) {
        int r = idx >> 6, d = idx & 63;
        wfs[r][d] = wf[r * CQ + h * 64 + d];
        wms[r][d] = wm[r * CQ + h * 64 + d];
    }
    __syncthreads();
    for (int idx = tid; idx < 2048; idx += 256) {
        int i2 = idx >> 6, j = idx & 63;
        float s0 = 0.f, s1 = 0.f;
        #pragma unroll
        for (int d = 0; d < 64; d++) {
            s0 += wfs[2 * i2][d] * wms[j][d];
            s1 += wfs[2 * i2 + 1][d] * wms[j][d];
        }
        __nv_bfloat16 h0 = __float2bfloat16_rn(s0), h1 = __float2bfloat16_rn(s1);
        __nv_bfloat16 l0 = __float2bfloat16_rn(s0 - __bfloat162float(h0));
        __nv_bfloat16 l1 = __float2bfloat16_rn(s1 - __bfloat162float(h1));
        int n = h * 64 + j;
        uint32_t hp = pkb(h0, h1), lp = pkb(l0, l1);
        g_GtA[n * 64 + i2]      = hp;
        g_GtA[n * 64 + 32 + i2] = lp;
        g_GtB[n * 64 + i2]      = lp;
        g_GtB[n * 64 + 32 + i2] = hp;
    }
    if (tid < 64) {
        float s = 0.f;
        #pragma unroll
        for (int d = 0; d < 64; d++) s += wms[tid][d] * bf[h * 64 + d];
        g_u[h * 64 + tid] = s;
    }
}

// ---------------- kernel 1: LayerNorm -> bf16 split rows ----------------
__global__ __launch_bounds__(128) void ln_kernel(
    const float* __restrict__ src,
    const float* __restrict__ gamma, const float* __restrict__ beta,
    int which)
{
    __shared__ float gs[64], bs[64];
    int tid = threadIdx.x;
    if (tid < 64) { gs[tid] = gamma[tid]; bs[tid] = beta[tid]; }
    __syncthreads();

    int p = blockIdx.x * 128 + tid;
    float v[64];
    float mean = 0.f;
    #pragma unroll
    for (int c = 0; c < 64; c++) { v[c] = src[c * NPTS + p]; mean += v[c]; }
    mean *= (1.f / 64.f);
    float var = 0.f;
    #pragma unroll
    for (int c = 0; c < 64; c++) { float d = v[c] - mean; var += d * d; }
    float rstd = rsqrtf(var * (1.f / 64.f) + LNEPS);

    uint32_t* dst = which ? g_xmh : g_xfh;
    #pragma unroll
    for (int c8 = 0; c8 < 64; c8 += 8) {
        uint32_t hw[4], lw[4];
        #pragma unroll
        for (int j = 0; j < 4; j++) {
            int c = c8 + 2 * j;
            float y0 = (v[c] - mean) * rstd * gs[c] + bs[c];
            float y1 = (v[c + 1] - mean) * rstd * gs[c + 1] + bs[c + 1];
            __nv_bfloat16 h0 = __float2bfloat16_rn(y0), h1 = __float2bfloat16_rn(y1);
            __nv_bfloat16 l0 = __float2bfloat16_rn(y0 - __bfloat162float(h0));
            __nv_bfloat16 l1 = __float2bfloat16_rn(y1 - __bfloat162float(h1));
            hw[j] = pkb(h0, h1);
            lw[j] = pkb(l0, l1);
        }
        *(uint4*)&dst[p * 64 + (c8 >> 1)]      = make_uint4(hw[0], hw[1], hw[2], hw[3]);
        *(uint4*)&dst[p * 64 + 32 + (c8 >> 1)] = make_uint4(lw[0], lw[1], lw[2], lw[3]);
    }
}

// ---------------- kernel 2: qm GEMM via mma.sync bf16 (split; lo*lo dropped) ----------------
// R6 B-resident m-loop, 12 MMA steps. Epilogue staged through a 16 KB smem
// buffer: conflict-free STS scatter, then transposed drain with STG.128
// (8 lines / warp-instruction) into the permuted g_qmA fragment layout.
#define EPI_OFF 98304
#define GEMM_SMEM (98304 + 16384)

__global__ __launch_bounds__(256, 2) void qm_gemm_mma()
{
    extern __shared__ char smg[];
    __shared__ float su[128];
    int tid = threadIdx.x;
    int wid = tid >> 5, lane = tid & 31;
    int n0 = blockIdx.x * 128;
    int h0 = n0 >> 6;
    int p0 = blockIdx.y * 512;
    int wm = wid & 1, wn = wid >> 1;

    if (tid < 128) su[tid] = g_u[n0 + tid];

    uint32_t smb = smem_u32(smg);
    uint32_t* ep = (uint32_t*)(smg + EPI_OFF);
    const uint4* xf4 = (const uint4*)g_xfh;
    const uint4* GA  = (const uint4*)g_GtA;
    const uint4* GB  = (const uint4*)g_GtB;

    #pragma unroll
    for (int i = tid; i < 2048; i += 256) {
        int r = i >> 4, c = i & 15;
        uint32_t dst = r * 256 + ((c ^ (r & 7)) << 4);
        CP16(smb + 32768 + dst, &GA[(n0 + r) * 16 + c]);
        CP16(smb + 65536 + dst, &GB[(n0 + r) * 16 + c]);
    }
    #pragma unroll
    for (int i = tid; i < 1024; i += 256) {
        int r = i >> 4, c = i & 15;
        uint32_t dst = r * 256 + ((c ^ (r & 7)) << 4);
        CP16(smb + dst, &xf4[(p0 + r) * 16 + c]);
    }
    CP_COMMIT();

    int arow = wm * 32 + (lane & 15);
    int ach  = lane >> 4;
    int brow = wn * 32 + (lane & 7) + ((lane >> 4) << 3);
    int bch  = (lane >> 3) & 1;
    int g = lane >> 2, t4 = lane & 3;

    #pragma unroll 1
    for (int t = 0; t < 8; t++) {
        __syncthreads();
        if (t < 7) {
            uint32_t abase = ((t + 1) & 1) ? 16384u : 0u;
            int pr = p0 + (t + 1) * 64;
            #pragma unroll
            for (int i = tid; i < 1024; i += 256) {
                int r = i >> 4, c = i & 15;
                uint32_t dst = abase + r * 256 + ((c ^ (r & 7)) << 4);
                CP16(smb + dst, &xf4[(pr + r) * 16 + c]);
            }
            CP_COMMIT();
            CP_WAIT1();
        } else {
            CP_WAIT0();
        }
        __syncthreads();

        uint32_t abase = (t & 1) ? 16384u : 0u;
        float acc[2][4][4];
        #pragma unroll
        for (int mi = 0; mi < 2; mi++)
            #pragma unroll
            for (int ni = 0; ni < 4; ni++)
                #pragma unroll
                for (int e = 0; e < 4; e++) acc[mi][ni][e] = 0.f;

        // 12 steps: B1 chunks 0..3 (hi*hi) + B2 chunks 0..7 (hi*lo, lo*hi).
        #pragma unroll
        for (int s = 0; s < 12; s++) {
            int kk = (s < 4) ? s : (s - 4);
            uint32_t boff = (s < 4) ? 32768u : 65536u;
            uint32_t a[2][4];
            #pragma unroll
            for (int mi = 0; mi < 2; mi++) {
                int row = arow + mi * 16;
                int ch  = kk * 2 + ach;
                ldsm_x4(a[mi], smb + abase + row * 256 + ((ch ^ (row & 7)) << 4));
            }
            uint32_t b[2][4];
            #pragma unroll
            for (int nj = 0; nj < 2; nj++) {
                int row = brow + nj * 16;
                int ch  = kk * 2 + bch;
                ldsm_x4(b[nj], smb + boff + row * 256 + ((ch ^ (row & 7)) << 4));
            }
            #pragma unroll
            for (int mi = 0; mi < 2; mi++)
                #pragma unroll
                for (int nj = 0; nj < 2; nj++) {
                    mma_bf16(acc[mi][2 * nj + 0], a[mi], b[nj][0], b[nj][1]);
                    mma_bf16(acc[mi][2 * nj + 1], a[mi], b[nj][2], b[nj][3]);
                }
        }

        // ---- epilogue: smem-staged transpose into g_qmA ----
        #pragma unroll 1
        for (int mi = 0; mi < 2; mi++) {
            // STS scatter (conflict-free via rotation)
            int hh  = wn >> 1;
            int lpA = wm * 16 + g;
            int lpB = lpA + 8;
            #pragma unroll
            for (int ni = 0; ni < 4; ni++) {
                int nl  = wn * 32 + ni * 8 + 2 * t4;
                int cph = (wn & 1) * 16 + ni * 4 + t4;
                int rot = (cph + 4 * (lpA & 7) + 16 * hh) & 31;   // lpA&7 == lpB&7
                float u0 = su[nl], u1 = su[nl + 1];
                float v0 = acc[mi][ni][0] + u0, v1 = acc[mi][ni][1] + u1;
                float v2 = acc[mi][ni][2] + u0, v3 = acc[mi][ni][3] + u1;
                __nv_bfloat16 ah0 = __float2bfloat16_rn(v0), ah1 = __float2bfloat16_rn(v1);
                __nv_bfloat16 al0 = __float2bfloat16_rn(v0 - __bfloat162float(ah0));
                __nv_bfloat16 al1 = __float2bfloat16_rn(v1 - __bfloat162float(ah1));
                __nv_bfloat16 bh0 = __float2bfloat16_rn(v2), bh1 = __float2bfloat16_rn(v3);
                __nv_bfloat16 bl0 = __float2bfloat16_rn(v2 - __bfloat162float(bh0));
                __nv_bfloat16 bl1 = __float2bfloat16_rn(v3 - __bfloat162float(bh1));
                int baseA = lpA * 128 + hh * 64 + rot;
                int baseB = lpB * 128 + hh * 64 + rot;
                ep[baseA]      = pkb(ah0, ah1);
                ep[baseA + 32] = pkb(al0, al1);
                ep[baseB]      = pkb(bh0, bh1);
                ep[baseB + 32] = pkb(bl0, bl1);
            }
            __syncthreads();
            // drain: transposed mapping, STG.128, 8 lines per warp-instruction
            #pragma unroll
            for (int jp = 0; jp < 4; jp++) {
                int id   = jp * 256 + tid;
                int lp   = id >> 5;
                int sub  = (id >> 2) & 7;
                int cj   = id & 3;
                int hh2  = sub >> 2, t4c = sub & 3;
                int hilo = cj >> 1,  cc  = cj & 1;
                uint32_t w[4];
                #pragma unroll
                for (int k = 0; k < 4; k++) {
                    int cph = 16 * cc + 4 * k + t4c;
                    w[k] = ep[lp * 128 + hh2 * 64 + hilo * 32 +
                              ((cph + 4 * (lp & 7) + 16 * hh2) & 31)];
                }
                int wmm = lp >> 4, rem = lp & 15;
                int P   = p0 + t * 64 + wmm * 32 + mi * 16 + rem;
                int h   = h0 + hh2;
                int ln  = (h & 7) * 4 + t4c;
                int hb  = h >> 3;
                int off = ln * 32 + hb * 16 + hilo * 8 + cc * 4;
                *(uint4*)&g_qmA[(long)P * 1024 + off] = make_uint4(w[0], w[1], w[2], w[3]);
            }
            __syncthreads();
        }
    }
}

// ---------------- kernel 3: HMMA neighborhood attention (48 MMA/pt) ----------------
#define TSC 17
#define YSC 579
#define ZSC 2321
#define SCRC 9283
#define HALO_BYTES (9303 * 16)

__global__ __launch_bounds__(256) void attn_kernel(
    const float* __restrict__ rpb, float* __restrict__ out)
{
    extern __shared__ uint4 halo4[];
    __shared__ float rpb_s[NHD * 27];
    int tid = threadIdx.x;
    int z0 = (blockIdx.x >> 4) * 2;
    int y0 = (blockIdx.x & 15) * 2;

    for (int i = tid; i < NHD * 27; i += 256) rpb_s[i] = rpb[i];

    const uint4* xmh4 = (const uint4*)g_xmh;
    for (int i = tid; i < 8704; i += 256) {
        int pos = i >> 4, c = i & 15;
        int z = pos / 136;
        int r = pos - z * 136;
        int y = r / 34;
        int t = r - y * 34;
        int gz = z0 - 1 + z, gy = y0 - 1 + y, gt = t - 1;
        uint4 v = make_uint4(0, 0, 0, 0);
        if ((unsigned)gz < 32u && (unsigned)gy < 32u && (unsigned)gt < 32u)
            v = xmh4[(gz * 1024 + gy * 32 + gt) * 16 + c];
        halo4[z * ZSC + y * YSC + t * TSC + c] = v;
    }
    for (int i = tid; i < 20; i += 256) halo4[SCRC + i] = make_uint4(0, 0, 0, 0);
    __syncthreads();

    int warp = tid >> 5, lane = tid & 31;
    int pz = warp & 1, py = (warp >> 1) & 1, th = warp >> 2;
    int g = lane >> 2, t4 = lane & 3;

    int orow  = (lane & 7) + ((lane >> 4) << 3);
    int bhalf = (lane >> 3) & 1;
    int brel[2], bsel[2];
    #pragma unroll
    for (int ng = 0; ng < 2; ng++) {
        int o = orow + ng * 16;
        if (o < 27) {
            int dz = o / 9, rr = o - dz * 9, dy = rr / 3, dx = rr - dy * 3;
            brel[ng] = dz * ZSC + dy * YSC + dx * TSC;
            bsel[ng] = 1;
        } else {
            brel[ng] = SCRC + (o - 27);
            bsel[ng] = 0;
        }
    }
    uint32_t halob = smem_u32(halo4);

    float rpbA[8], rpbB[8], wz[8], wy[8], wt[8], msk[8];
    #pragma unroll
    for (int i = 0; i < 8; i++) {
        int nt = i >> 1, j = i & 1, o = nt * 8 + 2 * t4 + j;
        if (o < 27) {
            int dz = o / 9, rr = o - dz * 9, dy = rr / 3, dx = rr - dy * 3;
            rpbA[i] = rpb_s[g * 27 + o];
            rpbB[i] = rpb_s[(g + 8) * 27 + o];
            wz[i] = (float)(dz - 1); wy[i] = (float)(dy - 1); wt[i] = (float)(dx - 1);
            msk[i] = 1.f;
        } else {
            rpbA[i] = 0.f; rpbB[i] = 0.f; wz[i] = 0.f; wy[i] = 0.f; wt[i] = 0.f; msk[i] = 0.f;
        }
    }

    const uint4* qmA4 = (const uint4*)g_qmA;
    int gp0 = (z0 + pz) * 1024 + (y0 + py) * 32 + th * 16;
    int pb0 = pz * ZSC + py * YSC + (th * 16) * TSC;

    uint4 A4[8], A4n[8];
    {
        const uint4* ap = &qmA4[((long)gp0 * 32 + lane) * 8];
        #pragma unroll
        for (int j = 0; j < 8; j++) A4[j] = ap[j];
    }

    #pragma unroll 1
    for (int i16 = 0; i16 < 16; i16++) {
        int gp = gp0 + i16;
        int pbase = pb0 + i16 * TSC;

        if (i16 < 15) {
            const uint4* ap = &qmA4[((long)(gp + 1) * 32 + lane) * 8];
            #pragma unroll
            for (int j = 0; j < 8; j++) A4n[j] = ap[j];
        }

        uint32_t b[2][8][4];
        #pragma unroll
        for (int ng = 0; ng < 2; ng++) {
            int basech = bsel[ng] * pbase + brel[ng] + bhalf;
            #pragma unroll
            for (int kc = 0; kc < 8; kc++)
                ldsm_x4(b[ng][kc], halob + (uint32_t)(basech + kc * 2) * 16u);
        }

        float acc[4][4];
        #pragma unroll
        for (int nt = 0; nt < 4; nt++)
            #pragma unroll
            for (int e = 0; e < 4; e++) acc[nt][e] = 0.f;

        const uint32_t* aw = (const uint32_t*)A4;
        #pragma unroll
        for (int kc = 0; kc < 4; kc++) {
            int u  = kc >> 1;
            int c0 = 2 * (kc & 1);
            uint32_t ah[4], al[4];
            ah[0] = aw[u * 4 + c0];           ah[1] = aw[(4 + u) * 4 + c0];
            ah[2] = aw[u * 4 + c0 + 1];       ah[3] = aw[(4 + u) * 4 + c0 + 1];
            int ul = 2 + u;
            al[0] = aw[ul * 4 + c0];          al[1] = aw[(4 + ul) * 4 + c0];
            al[2] = aw[ul * 4 + c0 + 1];      al[3] = aw[(4 + ul) * 4 + c0 + 1];
            #pragma unroll
            for (int nt = 0; nt < 4; nt++) {
                int ng = nt >> 1, hf = (nt & 1) * 2;
                mma_bf16(acc[nt], ah, b[ng][kc][hf],     b[ng][kc][hf + 1]);      // hi*hi
                mma_bf16(acc[nt], ah, b[ng][kc + 4][hf], b[ng][kc + 4][hf + 1]);  // hi*lo
                mma_bf16(acc[nt], al, b[ng][kc][hf],     b[ng][kc][hf + 1]);      // lo*hi
            }
        }

        float S0 = 0.f, Z0 = 0.f, Y0 = 0.f, T0 = 0.f;
        float S1 = 0.f, Z1 = 0.f, Y1 = 0.f, T1 = 0.f;
        #pragma unroll
        for (int i = 0; i < 8; i++) {
            int nt = i >> 1, j = i & 1;
            float e0 = __expf(acc[nt][j]     + rpbA[i]) * msk[i];
            float e1 = __expf(acc[nt][2 + j] + rpbB[i]) * msk[i];
            S0 += e0; Z0 += e0 * wz[i]; Y0 += e0 * wy[i]; T0 += e0 * wt[i];
            S1 += e1; Z1 += e1 * wz[i]; Y1 += e1 * wy[i]; T1 += e1 * wt[i];
        }
        #pragma unroll
        for (int m = 1; m < 4; m <<= 1) {
            S0 += __shfl_xor_sync(0xffffffffu, S0, m);
            Z0 += __shfl_xor_sync(0xffffffffu, Z0, m);
            Y0 += __shfl_xor_sync(0xffffffffu, Y0, m);
            T0 += __shfl_xor_sync(0xffffffffu, T0, m);
            S1 += __shfl_xor_sync(0xffffffffu, S1, m);
            Z1 += __shfl_xor_sync(0xffffffffu, Z1, m);
            Y1 += __shfl_xor_sync(0xffffffffu, Y1, m);
            T1 += __shfl_xor_sync(0xffffffffu, T1, m);
        }
        if (t4 == 0) {
            float i0 = 1.f / S0, i1 = 1.f / S1;
            out[(g * 3 + 0) * NPTS + gp] = Z0 * i0;
            out[(g * 3 + 1) * NPTS + gp] = Y0 * i0;
            out[(g * 3 + 2) * NPTS + gp] = T0 * i0;
            out[((g + 8) * 3 + 0) * NPTS + gp] = Z1 * i1;
            out[((g + 8) * 3 + 1) * NPTS + gp] = Y1 * i1;
            out[((g + 8) * 3 + 2) * NPTS + gp] = T1 * i1;
        }

        #pragma unroll
        for (int j = 0; j < 8; j++) A4[j] = A4n[j];
    }
}

// ---------------- launch ----------------
extern "C" void kernel_launch(void* const* d_in, const int* in_sizes, int n_in,
                              void* d_out, int out_size)
{
    const float* F       = (const float*)d_in[0];
    const float* M       = (const float*)d_in[1];
    const float* gamma_f = (const float*)d_in[2];
    const float* beta_f  = (const float*)d_in[3];
    const float* w_f     = (const float*)d_in[4];
    const float* b_f     = (const float*)d_in[5];
    const float* gamma_m = (const float*)d_in[6];
    const float* beta_m  = (const float*)d_in[7];
    const float* w_m     = (const float*)d_in[8];
    /* b_m (d_in[9]) is softmax-invariant and drops out */
    const float* rpb     = (const float*)d_in[10];
    float* out = (float*)d_out;

    precompute_kernel<<<16, 256>>>(w_f, w_m, b_f);
    ln_kernel<<<NPTS / 128, 128>>>(F, gamma_f, beta_f, 0);
    ln_kernel<<<NPTS / 128, 128>>>(M, gamma_m, beta_m, 1);

    cudaFuncSetAttribute(qm_gemm_mma, cudaFuncAttributeMaxDynamicSharedMemorySize, GEMM_SMEM);
    qm_gemm_mma<<<dim3(8, 64), 256, GEMM_SMEM>>>();

    cudaFuncSetAttribute(attn_kernel, cudaFuncAttributeMaxDynamicSharedMemorySize, HALO_BYTES);
    attn_kernel<<<256, 256, HALO_BYTES>>>(rpb, out);
}

// round 14
// speedup vs baseline: 1.7160x; 1.0855x over previous
#include <cuda_runtime.h>
#include <cuda_bf16.h>
#include <cstdint>
#include <math.h>

#define NPTS  32768
#define CIN   64
#define NHD   16
#define CQ    1024
#define LNEPS 1e-5f

// ---------------- helpers ----------------
__device__ __forceinline__ uint32_t smem_u32(const void* p) {
    uint32_t a;
    asm("{ .reg .u64 t; cvta.to.shared.u64 t, %1; cvt.u32.u64 %0, t; }" : "=r"(a) : "l"(p));
    return a;
}
__device__ __forceinline__ void ldsm_x4(uint32_t r[4], uint32_t addr) {
    asm volatile("ldmatrix.sync.aligned.m8n8.x4.shared.b16 {%0,%1,%2,%3}, [%4];"
                 : "=r"(r[0]), "=r"(r[1]), "=r"(r[2]), "=r"(r[3]) : "r"(addr));
}
__device__ __forceinline__ void mma_bf16(float c[4], const uint32_t a[4], uint32_t b0, uint32_t b1) {
    asm volatile("mma.sync.aligned.m16n8k16.row.col.f32.bf16.bf16.f32 "
                 "{%0,%1,%2,%3}, {%4,%5,%6,%7}, {%8,%9}, {%0,%1,%2,%3};"
                 : "+f"(c[0]), "+f"(c[1]), "+f"(c[2]), "+f"(c[3])
                 : "r"(a[0]), "r"(a[1]), "r"(a[2]), "r"(a[3]), "r"(b0), "r"(b1));
}
__device__ __forceinline__ uint32_t pkb(__nv_bfloat16 a, __nv_bfloat16 b) {
    return (uint32_t)__bfloat16_as_ushort(a) | ((uint32_t)__bfloat16_as_ushort(b) << 16);
}
#define CP16(dst, src) \
    asm volatile("cp.async.ca.shared.global [%0], [%1], 16;" :: "r"((uint32_t)(dst)), "l"(src))
#define CP_COMMIT() asm volatile("cp.async.commit_group;")
#define CP_WAIT0()  asm volatile("cp.async.wait_group 0;" ::: "memory")
#define CP_WAIT1()  asm volatile("cp.async.wait_group 1;" ::: "memory")

// ---------------- scratch ----------------
__device__ __align__(16) uint32_t g_xfh [NPTS * 64];   // LN(F) bf16 split, [p][word]
__device__ __align__(16) uint32_t g_xmh [NPTS * 64];   // LN(M) bf16 split
// qm bf16 split, per point 1024 words:
// word = ln*32 + hb*16 + hilo*8 + cc*4 + k  holds channel pair cph=16cc+4k+t4,
// ln = (h&7)*4 + t4, hb = h>>3.  Attention lane L reads words 32L..32L+31.
__device__ __align__(16) uint32_t g_qmA [NPTS * 1024];
__device__ __align__(16) uint32_t g_GtA [CQ * 64];     // [n][word]: [hi | lo]
__device__ __align__(16) uint32_t g_GtB [CQ * 64];     // [n][word]: [lo | hi]
__device__ float    g_u   [CQ];

// ---------------- kernel 0: fused weights G = Wf Wm^T (bf16 split) + u ----------------
__global__ __launch_bounds__(256) void precompute_kernel(
    const float* __restrict__ wf, const float* __restrict__ wm,
    const float* __restrict__ bf)
{
    int h = blockIdx.x;
    __shared__ float wfs[64][65];
    __shared__ float wms[64][65];
    int tid = threadIdx.x;
    for (int idx = tid; idx < 4096; idx += 256) {
        int r = idx >> 6, d = idx & 63;
        wfs[r][d] = wf[r * CQ + h * 64 + d];
        wms[r][d] = wm[r * CQ + h * 64 + d];
    }
    __syncthreads();
    for (int idx = tid; idx < 2048; idx += 256) {
        int i2 = idx >> 6, j = idx & 63;
        float s0 = 0.f, s1 = 0.f;
        #pragma unroll
        for (int d = 0; d < 64; d++) {
            s0 += wfs[2 * i2][d] * wms[j][d];
            s1 += wfs[2 * i2 + 1][d] * wms[j][d];
        }
        __nv_bfloat16 h0 = __float2bfloat16_rn(s0), h1 = __float2bfloat16_rn(s1);
        __nv_bfloat16 l0 = __float2bfloat16_rn(s0 - __bfloat162float(h0));
        __nv_bfloat16 l1 = __float2bfloat16_rn(s1 - __bfloat162float(h1));
        int n = h * 64 + j;
        uint32_t hp = pkb(h0, h1), lp = pkb(l0, l1);
        g_GtA[n * 64 + i2]      = hp;
        g_GtA[n * 64 + 32 + i2] = lp;
        g_GtB[n * 64 + i2]      = lp;
        g_GtB[n * 64 + 32 + i2] = hp;
    }
    if (tid < 64) {
        float s = 0.f;
        #pragma unroll
        for (int d = 0; d < 64; d++) s += wms[tid][d] * bf[h * 64 + d];
        g_u[h * 64 + tid] = s;
    }
}

// ---------------- kernel 1: LayerNorm -> bf16 split rows ----------------
__global__ __launch_bounds__(128) void ln_kernel(
    const float* __restrict__ src,
    const float* __restrict__ gamma, const float* __restrict__ beta,
    int which)
{
    __shared__ float gs[64], bs[64];
    int tid = threadIdx.x;
    if (tid < 64) { gs[tid] = gamma[tid]; bs[tid] = beta[tid]; }
    __syncthreads();

    int p = blockIdx.x * 128 + tid;
    float v[64];
    float mean = 0.f;
    #pragma unroll
    for (int c = 0; c < 64; c++) { v[c] = src[c * NPTS + p]; mean += v[c]; }
    mean *= (1.f / 64.f);
    float var = 0.f;
    #pragma unroll
    for (int c = 0; c < 64; c++) { float d = v[c] - mean; var += d * d; }
    float rstd = rsqrtf(var * (1.f / 64.f) + LNEPS);

    uint32_t* dst = which ? g_xmh : g_xfh;
    #pragma unroll
    for (int c8 = 0; c8 < 64; c8 += 8) {
        uint32_t hw[4], lw[4];
        #pragma unroll
        for (int j = 0; j < 4; j++) {
            int c = c8 + 2 * j;
            float y0 = (v[c] - mean) * rstd * gs[c] + bs[c];
            float y1 = (v[c + 1] - mean) * rstd * gs[c + 1] + bs[c + 1];
            __nv_bfloat16 h0 = __float2bfloat16_rn(y0), h1 = __float2bfloat16_rn(y1);
            __nv_bfloat16 l0 = __float2bfloat16_rn(y0 - __bfloat162float(h0));
            __nv_bfloat16 l1 = __float2bfloat16_rn(y1 - __bfloat162float(h1));
            hw[j] = pkb(h0, h1);
            lw[j] = pkb(l0, l1);
        }
        *(uint4*)&dst[p * 64 + (c8 >> 1)]      = make_uint4(hw[0], hw[1], hw[2], hw[3]);
        *(uint4*)&dst[p * 64 + 32 + (c8 >> 1)] = make_uint4(lw[0], lw[1], lw[2], lw[3]);
    }
}

// ---------------- kernel 2: qm GEMM via mma.sync bf16 (split; lo*lo dropped) ----------------
// R6 B-resident m-loop, 12 MMA steps. Direct epilogue: the C-fragment's 4 ni
// words are CONSECUTIVE in the g_qmA layout -> 8 STG.128 per thread per tile,
// no smem staging, no extra syncs.
#define GEMM_SMEM (98304)

__global__ __launch_bounds__(256, 2) void qm_gemm_mma()
{
    extern __shared__ char smg[];
    __shared__ float su[128];
    int tid = threadIdx.x;
    int wid = tid >> 5, lane = tid & 31;
    int n0 = blockIdx.x * 128;
    int h0 = n0 >> 6;
    int p0 = blockIdx.y * 512;
    int wm = wid & 1, wn = wid >> 1;

    if (tid < 128) su[tid] = g_u[n0 + tid];

    uint32_t smb = smem_u32(smg);
    const uint4* xf4 = (const uint4*)g_xfh;
    const uint4* GA  = (const uint4*)g_GtA;
    const uint4* GB  = (const uint4*)g_GtB;

    #pragma unroll
    for (int i = tid; i < 2048; i += 256) {
        int r = i >> 4, c = i & 15;
        uint32_t dst = r * 256 + ((c ^ (r & 7)) << 4);
        CP16(smb + 32768 + dst, &GA[(n0 + r) * 16 + c]);
        CP16(smb + 65536 + dst, &GB[(n0 + r) * 16 + c]);
    }
    #pragma unroll
    for (int i = tid; i < 1024; i += 256) {
        int r = i >> 4, c = i & 15;
        uint32_t dst = r * 256 + ((c ^ (r & 7)) << 4);
        CP16(smb + dst, &xf4[(p0 + r) * 16 + c]);
    }
    CP_COMMIT();

    int arow = wm * 32 + (lane & 15);
    int ach  = lane >> 4;
    int brow = wn * 32 + (lane & 7) + ((lane >> 4) << 3);
    int bch  = (lane >> 3) & 1;
    int g = lane >> 2, t4 = lane & 3;

    // epilogue addressing (invariant across tiles)
    int hh = wn >> 1;
    int h  = h0 + hh;
    int ln = (h & 7) * 4 + t4;
    int hb = h >> 3;
    int cc = wn & 1;
    int baseoff = ln * 32 + hb * 16 + cc * 4;

    #pragma unroll 1
    for (int t = 0; t < 8; t++) {
        __syncthreads();
        if (t < 7) {
            uint32_t abase = ((t + 1) & 1) ? 16384u : 0u;
            int pr = p0 + (t + 1) * 64;
            #pragma unroll
            for (int i = tid; i < 1024; i += 256) {
                int r = i >> 4, c = i & 15;
                uint32_t dst = abase + r * 256 + ((c ^ (r & 7)) << 4);
                CP16(smb + dst, &xf4[(pr + r) * 16 + c]);
            }
            CP_COMMIT();
            CP_WAIT1();
        } else {
            CP_WAIT0();
        }
        __syncthreads();

        uint32_t abase = (t & 1) ? 16384u : 0u;
        float acc[2][4][4];
        #pragma unroll
        for (int mi = 0; mi < 2; mi++)
            #pragma unroll
            for (int ni = 0; ni < 4; ni++)
                #pragma unroll
                for (int e = 0; e < 4; e++) acc[mi][ni][e] = 0.f;

        // 12 steps: B1 chunks 0..3 (hi*hi) + B2 chunks 0..7 (hi*lo, lo*hi)
        #pragma unroll
        for (int s = 0; s < 12; s++) {
            int kk = (s < 4) ? s : (s - 4);
            uint32_t boff = (s < 4) ? 32768u : 65536u;
            uint32_t a[2][4];
            #pragma unroll
            for (int mi = 0; mi < 2; mi++) {
                int row = arow + mi * 16;
                int ch  = kk * 2 + ach;
                ldsm_x4(a[mi], smb + abase + row * 256 + ((ch ^ (row & 7)) << 4));
            }
            uint32_t b[2][4];
            #pragma unroll
            for (int nj = 0; nj < 2; nj++) {
                int row = brow + nj * 16;
                int ch  = kk * 2 + bch;
                ldsm_x4(b[nj], smb + boff + row * 256 + ((ch ^ (row & 7)) << 4));
            }
            #pragma unroll
            for (int mi = 0; mi < 2; mi++)
                #pragma unroll
                for (int nj = 0; nj < 2; nj++) {
                    mma_bf16(acc[mi][2 * nj + 0], a[mi], b[nj][0], b[nj][1]);
                    mma_bf16(acc[mi][2 * nj + 1], a[mi], b[nj][2], b[nj][3]);
                }
        }

        // ---- direct epilogue: 8 STG.128 ----
        #pragma unroll
        for (int mi = 0; mi < 2; mi++) {
            int pA = p0 + t * 64 + wm * 32 + mi * 16 + g;
            uint32_t ahw[4], alw[4], bhw[4], blw[4];
            #pragma unroll
            for (int ni = 0; ni < 4; ni++) {
                int nl = wn * 32 + ni * 8 + 2 * t4;
                float u0 = su[nl], u1 = su[nl + 1];
                float v0 = acc[mi][ni][0] + u0, v1 = acc[mi][ni][1] + u1;
                float v2 = acc[mi][ni][2] + u0, v3 = acc[mi][ni][3] + u1;
                __nv_bfloat16 ah0 = __float2bfloat16_rn(v0), ah1 = __float2bfloat16_rn(v1);
                __nv_bfloat16 al0 = __float2bfloat16_rn(v0 - __bfloat162float(ah0));
                __nv_bfloat16 al1 = __float2bfloat16_rn(v1 - __bfloat162float(ah1));
                __nv_bfloat16 bh0 = __float2bfloat16_rn(v2), bh1 = __float2bfloat16_rn(v3);
                __nv_bfloat16 bl0 = __float2bfloat16_rn(v2 - __bfloat162float(bh0));
                __nv_bfloat16 bl1 = __float2bfloat16_rn(v3 - __bfloat162float(bh1));
                ahw[ni] = pkb(ah0, ah1);
                alw[ni] = pkb(al0, al1);
                bhw[ni] = pkb(bh0, bh1);
                blw[ni] = pkb(bl0, bl1);
            }
            *(uint4*)&g_qmA[(long)pA * 1024 + baseoff]           = make_uint4(ahw[0], ahw[1], ahw[2], ahw[3]);
            *(uint4*)&g_qmA[(long)pA * 1024 + baseoff + 8]       = make_uint4(alw[0], alw[1], alw[2], alw[3]);
            *(uint4*)&g_qmA[(long)(pA + 8) * 1024 + baseoff]     = make_uint4(bhw[0], bhw[1], bhw[2], bhw[3]);
            *(uint4*)&g_qmA[(long)(pA + 8) * 1024 + baseoff + 8] = make_uint4(blw[0], blw[1], blw[2], blw[3]);
        }
    }
}

// ---------------- kernel 3: HMMA neighborhood attention (48 MMA/pt, low-reg) ----------------
// ldsm interleaved with mma per kc: live B regs 16 (vs 64) to avoid spills.
#define TSC 17
#define YSC 579
#define ZSC 2321
#define SCRC 9283
#define HALO_BYTES (9303 * 16)

__global__ __launch_bounds__(256) void attn_kernel(
    const float* __restrict__ rpb, float* __restrict__ out)
{
    extern __shared__ uint4 halo4[];
    __shared__ float rpb_s[NHD * 27];
    int tid = threadIdx.x;
    int z0 = (blockIdx.x >> 4) * 2;
    int y0 = (blockIdx.x & 15) * 2;

    for (int i = tid; i < NHD * 27; i += 256) rpb_s[i] = rpb[i];

    const uint4* xmh4 = (const uint4*)g_xmh;
    for (int i = tid; i < 8704; i += 256) {
        int pos = i >> 4, c = i & 15;
        int z = pos / 136;
        int r = pos - z * 136;
        int y = r / 34;
        int t = r - y * 34;
        int gz = z0 - 1 + z, gy = y0 - 1 + y, gt = t - 1;
        uint4 v = make_uint4(0, 0, 0, 0);
        if ((unsigned)gz < 32u && (unsigned)gy < 32u && (unsigned)gt < 32u)
            v = xmh4[(gz * 1024 + gy * 32 + gt) * 16 + c];
        halo4[z * ZSC + y * YSC + t * TSC + c] = v;
    }
    for (int i = tid; i < 20; i += 256) halo4[SCRC + i] = make_uint4(0, 0, 0, 0);
    __syncthreads();

    int warp = tid >> 5, lane = tid & 31;
    int pz = warp & 1, py = (warp >> 1) & 1, th = warp >> 2;
    int g = lane >> 2, t4 = lane & 3;

    int orow  = (lane & 7) + ((lane >> 4) << 3);
    int bhalf = (lane >> 3) & 1;
    int brel[2], bsel[2];
    #pragma unroll
    for (int ng = 0; ng < 2; ng++) {
        int o = orow + ng * 16;
        if (o < 27) {
            int dz = o / 9, rr = o - dz * 9, dy = rr / 3, dx = rr - dy * 3;
            brel[ng] = dz * ZSC + dy * YSC + dx * TSC;
            bsel[ng] = 1;
        } else {
            brel[ng] = SCRC + (o - 27);
            bsel[ng] = 0;
        }
    }
    uint32_t halob = smem_u32(halo4);

    float rpbA[8], rpbB[8], wz[8], wy[8], wt[8], msk[8];
    #pragma unroll
    for (int i = 0; i < 8; i++) {
        int nt = i >> 1, j = i & 1, o = nt * 8 + 2 * t4 + j;
        if (o < 27) {
            int dz = o / 9, rr = o - dz * 9, dy = rr / 3, dx = rr - dy * 3;
            rpbA[i] = rpb_s[g * 27 + o];
            rpbB[i] = rpb_s[(g + 8) * 27 + o];
            wz[i] = (float)(dz - 1); wy[i] = (float)(dy - 1); wt[i] = (float)(dx - 1);
            msk[i] = 1.f;
        } else {
            rpbA[i] = 0.f; rpbB[i] = 0.f; wz[i] = 0.f; wy[i] = 0.f; wt[i] = 0.f; msk[i] = 0.f;
        }
    }

    const uint4* qmA4 = (const uint4*)g_qmA;
    int gp0 = (z0 + pz) * 1024 + (y0 + py) * 32 + th * 16;
    int pb0 = pz * ZSC + py * YSC + (th * 16) * TSC;

    uint4 A4[8], A4n[8];
    {
        const uint4* ap = &qmA4[((long)gp0 * 32 + lane) * 8];
        #pragma unroll
        for (int j = 0; j < 8; j++) A4[j] = ap[j];
    }

    #pragma unroll 1
    for (int i16 = 0; i16 < 16; i16++) {
        int gp = gp0 + i16;
        int pbase = pb0 + i16 * TSC;

        if (i16 < 15) {
            const uint4* ap = &qmA4[((long)(gp + 1) * 32 + lane) * 8];
            #pragma unroll
            for (int j = 0; j < 8; j++) A4n[j] = ap[j];
        }

        int basech0 = bsel[0] * pbase + brel[0] + bhalf;
        int basech1 = bsel[1] * pbase + brel[1] + bhalf;

        float acc[4][4];
        #pragma unroll
        for (int nt = 0; nt < 4; nt++)
            #pragma unroll
            for (int e = 0; e < 4; e++) acc[nt][e] = 0.f;

        const uint32_t* aw = (const uint32_t*)A4;
        #pragma unroll
        for (int kc = 0; kc < 4; kc++) {
            // B fragments for this kc (hi chunk) and kc+4 (lo chunk), both ng
            uint32_t bq[2][4], bq4[2][4];
            ldsm_x4(bq[0],  halob + (uint32_t)(basech0 + kc * 2) * 16u);
            ldsm_x4(bq[1],  halob + (uint32_t)(basech1 + kc * 2) * 16u);
            ldsm_x4(bq4[0], halob + (uint32_t)(basech0 + (kc + 4) * 2) * 16u);
            ldsm_x4(bq4[1], halob + (uint32_t)(basech1 + (kc + 4) * 2) * 16u);

            int u  = kc >> 1;
            int c0 = 2 * (kc & 1);
            uint32_t ah[4], al[4];
            ah[0] = aw[u * 4 + c0];           ah[1] = aw[(4 + u) * 4 + c0];
            ah[2] = aw[u * 4 + c0 + 1];       ah[3] = aw[(4 + u) * 4 + c0 + 1];
            int ul = 2 + u;
            al[0] = aw[ul * 4 + c0];          al[1] = aw[(4 + ul) * 4 + c0];
            al[2] = aw[ul * 4 + c0 + 1];      al[3] = aw[(4 + ul) * 4 + c0 + 1];
            #pragma unroll
            for (int nt = 0; nt < 4; nt++) {
                int ng = nt >> 1, hf = (nt & 1) * 2;
                mma_bf16(acc[nt], ah, bq[ng][hf],  bq[ng][hf + 1]);    // hi*hi
                mma_bf16(acc[nt], ah, bq4[ng][hf], bq4[ng][hf + 1]);   // hi*lo
                mma_bf16(acc[nt], al, bq[ng][hf],  bq[ng][hf + 1]);    // lo*hi
            }
        }

        float S0 = 0.f, Z0 = 0.f, Y0 = 0.f, T0 = 0.f;
        float S1 = 0.f, Z1 = 0.f, Y1 = 0.f, T1 = 0.f;
        #pragma unroll
        for (int i = 0; i < 8; i++) {
            int nt = i >> 1, j = i & 1;
            float e0 = __expf(acc[nt][j]     + rpbA[i]) * msk[i];
            float e1 = __expf(acc[nt][2 + j] + rpbB[i]) * msk[i];
            S0 += e0; Z0 += e0 * wz[i]; Y0 += e0 * wy[i]; T0 += e0 * wt[i];
            S1 += e1; Z1 += e1 * wz[i]; Y1 += e1 * wy[i]; T1 += e1 * wt[i];
        }
        #pragma unroll
        for (int m = 1; m < 4; m <<= 1) {
            S0 += __shfl_xor_sync(0xffffffffu, S0, m);
            Z0 += __shfl_xor_sync(0xffffffffu, Z0, m);
            Y0 += __shfl_xor_sync(0xffffffffu, Y0, m);
            T0 += __shfl_xor_sync(0xffffffffu, T0, m);
            S1 += __shfl_xor_sync(0xffffffffu, S1, m);
            Z1 += __shfl_xor_sync(0xffffffffu, Z1, m);
            Y1 += __shfl_xor_sync(0xffffffffu, Y1, m);
            T1 += __shfl_xor_sync(0xffffffffu, T1, m);
        }
        if (t4 == 0) {
            float i0 = 1.f / S0, i1 = 1.f / S1;
            out[(g * 3 + 0) * NPTS + gp] = Z0 * i0;
            out[(g * 3 + 1) * NPTS + gp] = Y0 * i0;
            out[(g * 3 + 2) * NPTS + gp] = T0 * i0;
            out[((g + 8) * 3 + 0) * NPTS + gp] = Z1 * i1;
            out[((g + 8) * 3 + 1) * NPTS + gp] = Y1 * i1;
            out[((g + 8) * 3 + 2) * NPTS + gp] = T1 * i1;
        }

        #pragma unroll
        for (int j = 0; j < 8; j++) A4[j] = A4n[j];
    }
}

// ---------------- launch ----------------
extern "C" void kernel_launch(void* const* d_in, const int* in_sizes, int n_in,
                              void* d_out, int out_size)
{
    const float* F       = (const float*)d_in[0];
    const float* M       = (const float*)d_in[1];
    const float* gamma_f = (const float*)d_in[2];
    const float* beta_f  = (const float*)d_in[3];
    const float* w_f     = (const float*)d_in[4];
    const float* b_f     = (const float*)d_in[5];
    const float* gamma_m = (const float*)d_in[6];
    const float* beta_m  = (const float*)d_in[7];
    const float* w_m     = (const float*)d_in[8];
    /* b_m (d_in[9]) is softmax-invariant and drops out */
    const float* rpb     = (const float*)d_in[10];
    float* out = (float*)d_out;

    precompute_kernel<<<16, 256>>>(w_f, w_m, b_f);
    ln_kernel<<<NPTS / 128, 128>>>(F, gamma_f, beta_f, 0);
    ln_kernel<<<NPTS / 128, 128>>>(M, gamma_m, beta_m, 1);

    cudaFuncSetAttribute(qm_gemm_mma, cudaFuncAttributeMaxDynamicSharedMemorySize, GEMM_SMEM);
    qm_gemm_mma<<<dim3(8, 64), 256, GEMM_SMEM>>>();

    cudaFuncSetAttribute(attn_kernel, cudaFuncAttributeMaxDynamicSharedMemorySize, HALO_BYTES);
    attn_kernel<<<256, 256, HALO_BYTES>>>(rpb, out);
}